// round 6
// baseline (speedup 1.0000x reference)
#include <cuda_runtime.h>
#include <cuda_bf16.h>

// ---------------------------------------------------------------------------
// ColorCNN round 6: 512-thread persistent-tile K1 with full weight
// double-buffering.
//   k0_prep: w1/w2 -> rna-rounded tf32 (stored as f32) scratch.
//   k1_mlp:  MT=256 pixel tile, 16 warps x 16 rows. GEMM1(tf32 mma)->bias+relu
//            ->shfl permute->GEMM2->softmax->mask+partials. Both weight chunks
//            double-buffered; prefetch overlaps the whole chunk compute.
//   k2a/k2b: reductions + scalars. k3: mask @ wc (float4).
// ---------------------------------------------------------------------------

#define HWD   65536
#define NB    8
#define CFD   64
#define HIDD  512
#define KCD   64
#define MT    256
#define NTILES 2048
#define NTHR  512

#define SW1   136   // w1 chunk stride (8 mod 32 -> conflict-free B frags)
#define SW2   72    // w2 chunk stride (8 mod 32)
#define SAO   264   // feat staging stride (8 mod 32)

// smem float offsets
#define W1B0    0                    // 64*136 = 8704
#define W1B1    8704                 // 8704   (also feat rows 0..31 staging)
#define W2B0    17408                // 128*72 = 9216  (also MSK base)
#define W2B1    26624                // 9216   (also feat rows 32..63 staging)
#define B1_OFF  35840                // 512
#define B2_OFF  36352                // 64
#define IMG_OFF 36416                // 768
#define SMEM_FLOATS 37184
#define SMEM_BYTES  (SMEM_FLOATS * 4)   // 148736

// global scratch
__device__ float g_mask[(size_t)NB * KCD * HWD];
__device__ float g_w1c[CFD * HIDD];        // rna-rounded w1
__device__ float g_w2c[HIDD * KCD];        // rna-rounded w2
__device__ float g_wc_part[NTILES * 192];
__device__ float g_max_part[NTILES * 64];
__device__ float g_sum_part[NTILES * 64];
__device__ float g_wc[NB * 192];
__device__ float g_cmax[NB * KCD];
__device__ float g_cmean[NB * KCD];

__device__ __forceinline__ unsigned f2tf32(float v) {
    unsigned r;
    asm("cvt.rna.tf32.f32 %0, %1;" : "=r"(r) : "f"(v));
    return r;
}

__device__ __forceinline__ void mma8(float c[4], const unsigned a[4], const unsigned b[2]) {
    asm volatile(
        "mma.sync.aligned.m16n8k8.row.col.f32.tf32.tf32.f32 "
        "{%0,%1,%2,%3}, {%4,%5,%6,%7}, {%8,%9}, {%0,%1,%2,%3};"
        : "+f"(c[0]), "+f"(c[1]), "+f"(c[2]), "+f"(c[3])
        : "r"(a[0]), "r"(a[1]), "r"(a[2]), "r"(a[3]),
          "r"(b[0]), "r"(b[1]));
}

__device__ __forceinline__ void cpa16(unsigned dst, const void* src) {
    asm volatile("cp.async.cg.shared.global [%0], [%1], 16;" :: "r"(dst), "l"(src));
}
#define CP_COMMIT() asm volatile("cp.async.commit_group;")
#define CP_WAIT0()  asm volatile("cp.async.wait_group 0;")

// ---------------------------------------------------------------------------
// k0_prep: round weights to tf32 (rna) once.
// ---------------------------------------------------------------------------
__global__ __launch_bounds__(256) void k0_prep(
    const float* __restrict__ w1, const float* __restrict__ w2)
{
    int i = blockIdx.x * 256 + threadIdx.x;
    if (i < CFD * HIDD)
        g_w1c[i] = __uint_as_float(f2tf32(w1[i]));
    int j = i - CFD * HIDD;
    if (j >= 0 && j < HIDD * KCD)
        g_w2c[j] = __uint_as_float(f2tf32(w2[j]));
}

// ---------------------------------------------------------------------------
__global__ __launch_bounds__(NTHR, 1) void k1_mlp(
    const float* __restrict__ feat, const float* __restrict__ img,
    const float* __restrict__ b1, const float* __restrict__ b2)
{
    extern __shared__ float sm[];
    unsigned smb;
    asm("{ .reg .u64 t; cvta.to.shared.u64 t, %1; cvt.u32.u64 %0, t; }"
        : "=r"(smb) : "l"(sm));

    const int tid  = threadIdx.x;
    const int lane = tid & 31;
    const int wrp  = tid >> 5;
    const int gid  = lane >> 2;
    const int tig  = lane & 3;
    const int tile = blockIdx.x;
    const int b    = tile >> 8;               // 256 tiles per image
    const int pix0 = (tile & 255) * MT;
    const int m0   = wrp * 16;                // 16 warps x 16 rows = 256

    const float* featb = feat + (size_t)b * CFD * HWD + pix0;

    // ---- prologue: feat -> buf1 regions, w1[0]/w2[0] -> buf0, all async ----
    for (int it = tid; it < 4096; it += NTHR) {         // feat: 64 rows x 256
        int r = it >> 6, c16 = (it & 63) << 2;
        int base = (r < 32) ? (W1B1 + r * SAO) : (W2B1 + (r - 32) * SAO);
        cpa16(smb + (unsigned)(base + c16) * 4u, featb + (size_t)r * HWD + c16);
    }
    for (int it = tid; it < 2048; it += NTHR) {         // w1 chunk 0: 64 x 128
        int r = it >> 5, c16 = (it & 31) << 2;
        cpa16(smb + (unsigned)(W1B0 + r * SW1 + c16) * 4u,
              g_w1c + (size_t)r * HIDD + c16);
    }
    for (int it = tid; it < 2048; it += NTHR) {         // w2 chunk 0: 128 x 64
        int r = it >> 4, c16 = (it & 15) << 2;
        cpa16(smb + (unsigned)(W2B0 + r * SW2 + c16) * 4u,
              g_w2c + (size_t)r * KCD + c16);
    }
    CP_COMMIT();
    // biases + img via plain stores
    if (tid < HIDD) sm[B1_OFF + tid] = b1[tid];
    if (tid < KCD)  sm[B2_OFF + tid] = b2[tid];
    for (int e = tid; e < 3 * MT; e += NTHR)
        sm[IMG_OFF + e] = img[(size_t)b * 3 * HWD + (size_t)(e >> 8) * HWD + pix0 + (e & 255)];
    CP_WAIT0();
    __syncthreads();

    // ---- preload GEMM1 A fragments (feat, cvt.rna). kf<4 -> half0 ----
    unsigned af[8][4];
#pragma unroll
    for (int kf = 0; kf < 8; kf++) {
        int k0 = kf * 8 + tig;
        int base = (kf < 4) ? (W1B1 + k0 * SAO) : (W2B1 + (k0 - 32) * SAO);
        af[kf][0] = f2tf32(sm[base + m0 + gid]);
        af[kf][1] = f2tf32(sm[base + m0 + gid + 8]);
        af[kf][2] = f2tf32(sm[base + 4 * SAO + m0 + gid]);
        af[kf][3] = f2tf32(sm[base + 4 * SAO + m0 + gid + 8]);
    }
    __syncthreads();   // feat staging dead; buf1 regions reusable

    float lg[8][4];
#pragma unroll
    for (int t = 0; t < 8; t++) { lg[t][0] = lg[t][1] = lg[t][2] = lg[t][3] = 0.f; }

    // ---- HID chunk loop, double-buffered ----
    for (int ch = 0; ch < 4; ch++) {
        const int cur = ch & 1;
        const int w1b = cur ? W1B1 : W1B0;
        const int w2b = cur ? W2B1 : W2B0;
        if (ch < 3) {
            const int n1 = cur ? W1B0 : W1B1;
            const int n2 = cur ? W2B0 : W2B1;
            for (int it = tid; it < 2048; it += NTHR) {
                int r = it >> 5, c16 = (it & 31) << 2;
                cpa16(smb + (unsigned)(n1 + r * SW1 + c16) * 4u,
                      g_w1c + (size_t)r * HIDD + (ch + 1) * 128 + c16);
            }
            for (int it = tid; it < 2048; it += NTHR) {
                int r = it >> 4, c16 = (it & 15) << 2;
                cpa16(smb + (unsigned)(n2 + r * SW2 + c16) * 4u,
                      g_w2c + (size_t)((ch + 1) * 128 + r) * KCD + c16);
            }
            CP_COMMIT();
        }

#pragma unroll 1
        for (int nt = 0; nt < 16; nt++) {
            const int nc = nt * 8 + gid;
            float cA[4] = {0.f, 0.f, 0.f, 0.f};
            float cB[4] = {0.f, 0.f, 0.f, 0.f};
#pragma unroll
            for (int kf = 0; kf < 8; kf += 2) {
                unsigned bf[2];
                int k0 = kf * 8 + tig;
                bf[0] = __float_as_uint(sm[w1b + k0 * SW1 + nc]);
                bf[1] = __float_as_uint(sm[w1b + (k0 + 4) * SW1 + nc]);
                mma8(cA, af[kf], bf);
                int k1 = k0 + 8;
                bf[0] = __float_as_uint(sm[w1b + k1 * SW1 + nc]);
                bf[1] = __float_as_uint(sm[w1b + (k1 + 4) * SW1 + nc]);
                mma8(cB, af[kf + 1], bf);
            }
            // bias + relu + tf32 cvt
            int d0 = ch * 128 + nt * 8 + 2 * tig;
            float bb0 = sm[B1_OFF + d0], bb1 = sm[B1_OFF + d0 + 1];
            unsigned u0 = f2tf32(fmaxf(cA[0] + cB[0] + bb0, 0.f));
            unsigned u1 = f2tf32(fmaxf(cA[1] + cB[1] + bb1, 0.f));
            unsigned u2 = f2tf32(fmaxf(cA[2] + cB[2] + bb0, 0.f));
            unsigned u3 = f2tf32(fmaxf(cA[3] + cB[3] + bb1, 0.f));
            // permute GEMM1 C-frag -> GEMM2 A-frag via shuffles
            int base = lane & ~3;
            int s0l = base + (tig >> 1);
            int s1l = s0l + 2;
            unsigned a2[4];
            unsigned xa, xb;
            xa = __shfl_sync(0xffffffffu, u0, s0l);
            xb = __shfl_sync(0xffffffffu, u1, s0l);
            a2[0] = (tig & 1) ? xb : xa;              // H[gid][tig]
            xa = __shfl_sync(0xffffffffu, u2, s0l);
            xb = __shfl_sync(0xffffffffu, u3, s0l);
            a2[1] = (tig & 1) ? xb : xa;              // H[gid+8][tig]
            xa = __shfl_sync(0xffffffffu, u0, s1l);
            xb = __shfl_sync(0xffffffffu, u1, s1l);
            a2[2] = (tig & 1) ? xb : xa;              // H[gid][tig+4]
            xa = __shfl_sync(0xffffffffu, u2, s1l);
            xb = __shfl_sync(0xffffffffu, u3, s1l);
            a2[3] = (tig & 1) ? xb : xa;              // H[gid+8][tig+4]
            // GEMM2: logits += Hblk @ w2[rows nt*8..nt*8+8]
            int kr = nt * 8 + tig;
#pragma unroll
            for (int t = 0; t < 8; t++) {
                unsigned bf[2];
                bf[0] = __float_as_uint(sm[w2b + kr * SW2 + t * 8 + gid]);
                bf[1] = __float_as_uint(sm[w2b + (kr + 4) * SW2 + t * 8 + gid]);
                mma8(lg[t], a2, bf);
            }
        }

        if (ch < 3) {
            CP_WAIT0();
            __syncthreads();   // prefetched buffers ready; cur buffers done
        }
    }
    __syncthreads();   // final chunk reads done; W2 regions -> mask

    // ---- softmax over 64 classes (quad-level reductions) ----
    float* MSK = sm + W2B0;   // stride 65, 256 rows
    const int r0 = m0 + gid, r1 = r0 + 8;
    float mx0 = -1e30f, mx1 = -1e30f;
#pragma unroll
    for (int t = 0; t < 8; t++) {
        int col = t * 8 + 2 * tig;
        float bb0 = sm[B2_OFF + col], bb1 = sm[B2_OFF + col + 1];
        lg[t][0] += bb0; lg[t][1] += bb1; lg[t][2] += bb0; lg[t][3] += bb1;
        mx0 = fmaxf(mx0, fmaxf(lg[t][0], lg[t][1]));
        mx1 = fmaxf(mx1, fmaxf(lg[t][2], lg[t][3]));
    }
    mx0 = fmaxf(mx0, __shfl_xor_sync(0xffffffffu, mx0, 1));
    mx0 = fmaxf(mx0, __shfl_xor_sync(0xffffffffu, mx0, 2));
    mx1 = fmaxf(mx1, __shfl_xor_sync(0xffffffffu, mx1, 1));
    mx1 = fmaxf(mx1, __shfl_xor_sync(0xffffffffu, mx1, 2));
    float s0 = 0.f, s1 = 0.f;
#pragma unroll
    for (int t = 0; t < 8; t++) {
        lg[t][0] = __expf(lg[t][0] - mx0); s0 += lg[t][0];
        lg[t][1] = __expf(lg[t][1] - mx0); s0 += lg[t][1];
        lg[t][2] = __expf(lg[t][2] - mx1); s1 += lg[t][2];
        lg[t][3] = __expf(lg[t][3] - mx1); s1 += lg[t][3];
    }
    s0 += __shfl_xor_sync(0xffffffffu, s0, 1);
    s0 += __shfl_xor_sync(0xffffffffu, s0, 2);
    s1 += __shfl_xor_sync(0xffffffffu, s1, 1);
    s1 += __shfl_xor_sync(0xffffffffu, s1, 2);
    float inv0 = 1.f / s0, inv1 = 1.f / s1;
#pragma unroll
    for (int t = 0; t < 8; t++) {
        int col = t * 8 + 2 * tig;
        MSK[r0 * 65 + col]     = lg[t][0] * inv0;
        MSK[r0 * 65 + col + 1] = lg[t][1] * inv0;
        MSK[r1 * 65 + col]     = lg[t][2] * inv1;
        MSK[r1 * 65 + col + 1] = lg[t][3] * inv1;
    }
    __syncthreads();

    // ---- mask -> global (planar), per-tile partials ----
    size_t mbase = (size_t)b * KCD * HWD + pix0;
    for (int e = tid; e < KCD * MT; e += NTHR) {
        int k = e >> 8, i = e & 255;
        g_mask[mbase + (size_t)k * HWD + i] = MSK[i * 65 + k];
    }
    if (tid < 192) {
        int c = tid >> 6, k = tid & 63;
        float s = 0.f;
        for (int i = 0; i < MT; i++) s += sm[IMG_OFF + c * MT + i] * MSK[i * 65 + k];
        g_wc_part[tile * 192 + tid] = s;
    } else if (tid < 256) {
        int k = tid - 192;
        float mx = -1e30f, smv = 0.f;
        for (int i = 0; i < MT; i++) {
            float v = MSK[i * 65 + k];
            mx = fmaxf(mx, v); smv += v;
        }
        g_max_part[tile * 64 + k] = mx;
        g_sum_part[tile * 64 + k] = smv;
    }
}

// ---------------------------------------------------------------------------
// K2a: one warp per reduction job (256 tile-partials each).
// jobs: [0,1536) wc, [1536,2048) chan_max, [2048,2560) chan_mean
// ---------------------------------------------------------------------------
__global__ __launch_bounds__(256) void k2a_reduce() {
    int job  = blockIdx.x * 8 + (threadIdx.x >> 5);
    int lane = threadIdx.x & 31;
    if (job < 1536) {
        int b = job / 192, r = job % 192;
        const float* p = g_wc_part + (size_t)b * 256 * 192 + r;
        float s = 0.f;
        for (int i = lane; i < 256; i += 32) s += p[(size_t)i * 192];
        for (int o = 16; o; o >>= 1) s += __shfl_xor_sync(0xffffffffu, s, o);
        if (lane == 0) g_wc[job] = s * (1.f / HWD);
    } else if (job < 2048) {
        int j = job - 1536; int b = j >> 6, k = j & 63;
        const float* p = g_max_part + (size_t)b * 256 * 64 + k;
        float m = -1e30f;
        for (int i = lane; i < 256; i += 32) m = fmaxf(m, p[(size_t)i * 64]);
        for (int o = 16; o; o >>= 1) m = fmaxf(m, __shfl_xor_sync(0xffffffffu, m, o));
        if (lane == 0) g_cmax[j] = m;
    } else if (job < 2560) {
        int j = job - 2048; int b = j >> 6, k = j & 63;
        const float* p = g_sum_part + (size_t)b * 256 * 64 + k;
        float s = 0.f;
        for (int i = lane; i < 256; i += 32) s += p[(size_t)i * 64];
        for (int o = 16; o; o >>= 1) s += __shfl_xor_sync(0xffffffffu, s, o);
        if (lane == 0) g_cmean[j] = s * (1.f / HWD);
    }
}

// ---------------------------------------------------------------------------
__global__ __launch_bounds__(512) void k2b_scalars(float* __restrict__ out, int out_size) {
    __shared__ float red[512];
    __shared__ float cmn[512];
    __shared__ float stds[8];
    int t = threadIdx.x;
    red[t] = g_cmax[t];
    cmn[t] = g_cmean[t];
    __syncthreads();
    for (int s = 256; s > 0; s >>= 1) {
        if (t < s) red[t] += red[t + s];
        __syncthreads();
    }
    if (t < 8) {
        float m = 0.f;
        for (int k = 0; k < 64; k++) m += cmn[t * 64 + k];
        m *= (1.f / 64.f);
        float v = 0.f;
        for (int k = 0; k < 64; k++) { float d = cmn[t * 64 + k] - m; v += d * d; }
        stds[t] = sqrtf(v * (1.f / 63.f));
    }
    __syncthreads();
    if (t == 0) {
        float s = 0.f;
        for (int b = 0; b < 8; b++) s += stds[b];
        out[out_size - 2] = red[0] * (1.f / 512.f);
        out[out_size - 1] = s * (1.f / 8.f);
    }
}

// ---------------------------------------------------------------------------
// K3: transformed_img, float4-vectorized (4 pixels/thread).
// ---------------------------------------------------------------------------
__global__ __launch_bounds__(256) void k3_expand(float* __restrict__ out) {
    int q  = blockIdx.x * 256 + threadIdx.x;   // quad index (4 pixels)
    int b  = q >> 14;                          // 16384 quads per image
    int pl = (q & 16383) << 2;
    __shared__ float wcs[192];
    if (threadIdx.x < 192) wcs[threadIdx.x] = g_wc[b * 192 + threadIdx.x];
    __syncthreads();
    const float* mp = g_mask + (size_t)b * KCD * HWD + pl;
    float4 a0 = {0.f, 0.f, 0.f, 0.f};
    float4 a1 = {0.f, 0.f, 0.f, 0.f};
    float4 a2 = {0.f, 0.f, 0.f, 0.f};
#pragma unroll 8
    for (int k = 0; k < KCD; k++) {
        float4 m = *(const float4*)(mp + (size_t)k * HWD);
        float w0 = wcs[k], w1v = wcs[64 + k], w2v = wcs[128 + k];
        a0.x += m.x * w0;  a0.y += m.y * w0;  a0.z += m.z * w0;  a0.w += m.w * w0;
        a1.x += m.x * w1v; a1.y += m.y * w1v; a1.z += m.z * w1v; a1.w += m.w * w1v;
        a2.x += m.x * w2v; a2.y += m.y * w2v; a2.z += m.z * w2v; a2.w += m.w * w2v;
    }
    *(float4*)(out + ((size_t)b * 3 + 0) * HWD + pl) = a0;
    *(float4*)(out + ((size_t)b * 3 + 1) * HWD + pl) = a1;
    *(float4*)(out + ((size_t)b * 3 + 2) * HWD + pl) = a2;
}

// ---------------------------------------------------------------------------
extern "C" void kernel_launch(void* const* d_in, const int* in_sizes, int n_in,
                              void* d_out, int out_size) {
    const float* img  = (const float*)d_in[0];
    const float* feat = (const float*)d_in[1];
    const float* w1 = (const float*)d_in[3];
    const float* b1 = (const float*)d_in[4];
    const float* w2 = (const float*)d_in[5];
    const float* b2 = (const float*)d_in[6];
    float* out = (float*)d_out;

    cudaFuncSetAttribute(k1_mlp, cudaFuncAttributeMaxDynamicSharedMemorySize, SMEM_BYTES);

    k0_prep<<<256, 256>>>(w1, w2);
    k1_mlp<<<NTILES, NTHR, SMEM_BYTES>>>(feat, img, b1, b2);
    k2a_reduce<<<320, 256>>>();
    k2b_scalars<<<1, 512>>>(out, out_size);
    k3_expand<<<512, 256>>>(out);
}

// round 8
// speedup vs baseline: 1.8120x; 1.8120x over previous
#include <cuda_runtime.h>
#include <cuda_fp16.h>

// ---------------------------------------------------------------------------
// ColorCNN round 8 (= round-7 fp16 kernel resubmitted after infra flake):
// fp16 m16n8k16 mma pipeline (same 11-bit mantissa as tf32, half the LDS
// bytes, half the mma count, ZERO shuffles: the k16 C-fragment layout packs
// directly into the next GEMM's A-fragment).
//   k0_prep: w1/w2 -> rn-rounded half2 k-pair-packed scratch.
//   k1_mlp:  GEMM1(f16 mma)->bias+relu->pack->GEMM2(f16 mma)->softmax
//            -> fp16 mask scratch + fp32 per-tile partials.
//   k2a/k2b: reductions + scalars (fp32). k3: fp16 mask @ wc (half2 loads).
// ---------------------------------------------------------------------------

#define HWD   65536
#define NB    8
#define CFD   64
#define HIDD  512
#define KCD   64
#define MT    128
#define NTILES 4096

// word strides (8 mod 32 -> conflict-free fragment loads)
#define SW1   136   // w1 chunk: 32 kpair rows x 128 uint
#define SW2   72    // w2 chunk: 64 dpair rows x 64 uint
#define SAO   136   // feat tile: 64 rows x 128 f32

// smem word offsets
#define FEAT_OFF 0                    // 64*136 = 8704 (becomes MSK: 128*65)
#define W1S_OFF  8704                 // 32*136 = 4352
#define W2S_OFF  13056                // 64*72  = 4608
#define B1_OFF   17664                // 512
#define B2_OFF   18176                // 64
#define IMG_OFF  18240                // 384
#define SMEM_FLOATS 18624
#define SMEM_BYTES  (SMEM_FLOATS * 4)   // 74496 -> 2 CTAs/SM

// global scratch
__device__ __half g_maskh[(size_t)NB * KCD * HWD];     // 67 MB fp16 mask
__device__ unsigned g_w1h[32 * HIDD];                  // half2(w1[2kp][n], w1[2kp+1][n])
__device__ unsigned g_w2h[256 * KCD];                  // half2(w2[2dp][n], w2[2dp+1][n])
__device__ float g_wc_part[NTILES * 192];
__device__ float g_max_part[NTILES * 64];
__device__ float g_sum_part[NTILES * 64];
__device__ float g_wc[NB * 192];
__device__ float g_cmax[NB * KCD];
__device__ float g_cmean[NB * KCD];

// pack two f32 -> f16x2 (lo = first arg, hi = second), round-to-nearest
__device__ __forceinline__ unsigned packh2(float lo, float hi) {
    unsigned r;
    asm("cvt.rn.f16x2.f32 %0, %1, %2;" : "=r"(r) : "f"(hi), "f"(lo));
    return r;
}

__device__ __forceinline__ void mma16(float c[4], const unsigned a[4],
                                      unsigned b0, unsigned b1) {
    asm volatile(
        "mma.sync.aligned.m16n8k16.row.col.f32.f16.f16.f32 "
        "{%0,%1,%2,%3}, {%4,%5,%6,%7}, {%8,%9}, {%0,%1,%2,%3};"
        : "+f"(c[0]), "+f"(c[1]), "+f"(c[2]), "+f"(c[3])
        : "r"(a[0]), "r"(a[1]), "r"(a[2]), "r"(a[3]),
          "r"(b0), "r"(b1));
}

__device__ __forceinline__ void cpa16(unsigned dst, const void* src) {
    asm volatile("cp.async.cg.shared.global [%0], [%1], 16;" :: "r"(dst), "l"(src));
}
#define CP_COMMIT() asm volatile("cp.async.commit_group;")
#define CP_WAIT0()  asm volatile("cp.async.wait_group 0;")

// ---------------------------------------------------------------------------
// k0_prep: w1 [64x512] -> g_w1h [32][512] half2 k-pairs;
//          w2 [512x64] -> g_w2h [256][64] half2 d-pairs.  (rn rounding)
// ---------------------------------------------------------------------------
__global__ __launch_bounds__(256) void k0_prep(
    const float* __restrict__ w1, const float* __restrict__ w2)
{
    int i = blockIdx.x * 256 + threadIdx.x;
    if (i < 32 * HIDD) {
        int kp = i >> 9, n = i & 511;
        g_w1h[i] = packh2(w1[(2 * kp) * HIDD + n], w1[(2 * kp + 1) * HIDD + n]);
    }
    int j = i - 32 * HIDD;
    if (j >= 0 && j < 256 * KCD) {
        int dp = j >> 6, n = j & 63;
        g_w2h[j] = packh2(w2[(2 * dp) * KCD + n], w2[(2 * dp + 1) * KCD + n]);
    }
}

// ---------------------------------------------------------------------------
__global__ __launch_bounds__(256, 2) void k1_mlp(
    const float* __restrict__ feat, const float* __restrict__ img,
    const float* __restrict__ b1, const float* __restrict__ b2)
{
    extern __shared__ float sm[];
    unsigned* usm = (unsigned*)sm;
    unsigned smb;
    asm("{ .reg .u64 t; cvta.to.shared.u64 t, %1; cvt.u32.u64 %0, t; }"
        : "=r"(smb) : "l"(sm));

    const int tid  = threadIdx.x;
    const int lane = tid & 31;
    const int wrp  = tid >> 5;
    const int gid  = lane >> 2;
    const int tig  = lane & 3;
    const int tile = blockIdx.x;
    const int b    = tile >> 9;
    const int pix0 = (tile & 511) * MT;
    const int m0   = wrp * 16;

    const float* featb = feat + (size_t)b * CFD * HWD + pix0;

    // ---- prologue: feat(f32) + w1/w2 chunk 0 via cp.async ----
    for (int it = tid; it < 2048; it += 256) {          // feat 64 x 128 f32
        int r = it >> 5, c16 = (it & 31) << 2;
        cpa16(smb + (unsigned)(FEAT_OFF + r * SAO + c16) * 4u,
              featb + (size_t)r * HWD + c16);
    }
    for (int it = tid; it < 1024; it += 256) {          // w1 ch0: 32 x 128 uint
        int r = it >> 5, c4 = (it & 31) << 2;
        cpa16(smb + (unsigned)(W1S_OFF + r * SW1 + c4) * 4u,
              g_w1h + (size_t)r * HIDD + c4);
    }
    for (int it = tid; it < 1024; it += 256) {          // w2 ch0: 64 x 64 uint
        int r = it >> 4, c4 = (it & 15) << 2;
        cpa16(smb + (unsigned)(W2S_OFF + r * SW2 + c4) * 4u,
              g_w2h + (size_t)r * KCD + c4);
    }
    CP_COMMIT();
    for (int e = tid; e < HIDD; e += 256) sm[B1_OFF + e] = b1[e];
    if (tid < KCD) sm[B2_OFF + tid] = b2[tid];
    for (int e = tid; e < 3 * MT; e += 256)
        sm[IMG_OFF + e] = img[(size_t)b * 3 * HWD + (size_t)(e >> 7) * HWD + pix0 + (e & 127)];
    CP_WAIT0();
    __syncthreads();

    // ---- preload GEMM1 A fragments: feat -> fp16 packed, 4 k-frags ----
    unsigned af[4][4];
#pragma unroll
    for (int kf = 0; kf < 4; kf++) {
        int k0 = 16 * kf + 2 * tig;
        af[kf][0] = packh2(sm[FEAT_OFF + k0 * SAO + m0 + gid],
                           sm[FEAT_OFF + (k0 + 1) * SAO + m0 + gid]);
        af[kf][1] = packh2(sm[FEAT_OFF + k0 * SAO + m0 + gid + 8],
                           sm[FEAT_OFF + (k0 + 1) * SAO + m0 + gid + 8]);
        af[kf][2] = packh2(sm[FEAT_OFF + (k0 + 8) * SAO + m0 + gid],
                           sm[FEAT_OFF + (k0 + 9) * SAO + m0 + gid]);
        af[kf][3] = packh2(sm[FEAT_OFF + (k0 + 8) * SAO + m0 + gid + 8],
                           sm[FEAT_OFF + (k0 + 9) * SAO + m0 + gid + 8]);
    }

    float lg[8][4];
#pragma unroll
    for (int t = 0; t < 8; t++) { lg[t][0] = lg[t][1] = lg[t][2] = lg[t][3] = 0.f; }

    // ---- HID chunk loop (chunks of 128 cols), single-buffered weights ----
    for (int ch = 0; ch < 4; ch++) {
        if (ch > 0) {
            __syncthreads();   // prev chunk reads done
            for (int it = tid; it < 1024; it += 256) {
                int r = it >> 5, c4 = (it & 31) << 2;
                cpa16(smb + (unsigned)(W1S_OFF + r * SW1 + c4) * 4u,
                      g_w1h + (size_t)r * HIDD + ch * 128 + c4);
            }
            for (int it = tid; it < 1024; it += 256) {
                int r = it >> 4, c4 = (it & 15) << 2;
                cpa16(smb + (unsigned)(W2S_OFF + r * SW2 + c4) * 4u,
                      g_w2h + (size_t)(ch * 64 + r) * KCD + c4);
            }
            CP_COMMIT();
            CP_WAIT0();
            __syncthreads();
        }

        // 8 nt-pairs of (GEMM1 x2, GEMM2 K=16)
#pragma unroll 1
        for (int np = 0; np < 8; np++) {
            unsigned a2[4];
            // --- GEMM1 for nt = 2np and 2np+1 ---
#pragma unroll
            for (int half = 0; half < 2; half++) {
                const int nt = 2 * np + half;
                const int nc = nt * 8 + gid;
                float cA[4] = {0.f, 0.f, 0.f, 0.f};
                float cB[4] = {0.f, 0.f, 0.f, 0.f};
                {
                    unsigned b0 = usm[W1S_OFF + (tig)     * SW1 + nc];
                    unsigned b1 = usm[W1S_OFF + (tig + 4) * SW1 + nc];
                    mma16(cA, af[0], b0, b1);
                    b0 = usm[W1S_OFF + (tig + 8)  * SW1 + nc];
                    b1 = usm[W1S_OFF + (tig + 12) * SW1 + nc];
                    mma16(cB, af[1], b0, b1);
                    b0 = usm[W1S_OFF + (tig + 16) * SW1 + nc];
                    b1 = usm[W1S_OFF + (tig + 20) * SW1 + nc];
                    mma16(cA, af[2], b0, b1);
                    b0 = usm[W1S_OFF + (tig + 24) * SW1 + nc];
                    b1 = usm[W1S_OFF + (tig + 28) * SW1 + nc];
                    mma16(cB, af[3], b0, b1);
                }
                int d0 = ch * 128 + nt * 8 + 2 * tig;
                float bb0 = sm[B1_OFF + d0], bb1 = sm[B1_OFF + d0 + 1];
                float h0 = fmaxf(cA[0] + cB[0] + bb0, 0.f);
                float h1 = fmaxf(cA[1] + cB[1] + bb1, 0.f);
                float h2 = fmaxf(cA[2] + cB[2] + bb0, 0.f);
                float h3 = fmaxf(cA[3] + cB[3] + bb1, 0.f);
                // C-frag -> A-frag of GEMM2: direct pack, no shuffles
                a2[2 * half]     = packh2(h0, h1);   // rows gid,   cols 2tig(+1)
                a2[2 * half + 1] = packh2(h2, h3);   // rows gid+8
            }
            // --- GEMM2: logits += H[:, 16np..16np+16) @ w2 chunk rows ---
            const int r0 = 8 * np + tig;
#pragma unroll
            for (int t = 0; t < 8; t++) {
                unsigned b0 = usm[W2S_OFF + r0 * SW2 + t * 8 + gid];
                unsigned b1 = usm[W2S_OFF + (r0 + 4) * SW2 + t * 8 + gid];
                mma16(lg[t], a2, b0, b1);
            }
        }
    }
    __syncthreads();   // all weight reads done; FEAT region -> MSK

    // ---- softmax over 64 classes (quad-level reductions, fp32) ----
    float* MSK = sm + FEAT_OFF;   // stride 65, 128 rows
    const int r0 = m0 + gid, r1 = r0 + 8;
    float mx0 = -1e30f, mx1 = -1e30f;
#pragma unroll
    for (int t = 0; t < 8; t++) {
        int col = t * 8 + 2 * tig;
        float bb0 = sm[B2_OFF + col], bb1 = sm[B2_OFF + col + 1];
        lg[t][0] += bb0; lg[t][1] += bb1; lg[t][2] += bb0; lg[t][3] += bb1;
        mx0 = fmaxf(mx0, fmaxf(lg[t][0], lg[t][1]));
        mx1 = fmaxf(mx1, fmaxf(lg[t][2], lg[t][3]));
    }
    mx0 = fmaxf(mx0, __shfl_xor_sync(0xffffffffu, mx0, 1));
    mx0 = fmaxf(mx0, __shfl_xor_sync(0xffffffffu, mx0, 2));
    mx1 = fmaxf(mx1, __shfl_xor_sync(0xffffffffu, mx1, 1));
    mx1 = fmaxf(mx1, __shfl_xor_sync(0xffffffffu, mx1, 2));
    float s0 = 0.f, s1 = 0.f;
#pragma unroll
    for (int t = 0; t < 8; t++) {
        lg[t][0] = __expf(lg[t][0] - mx0); s0 += lg[t][0];
        lg[t][1] = __expf(lg[t][1] - mx0); s0 += lg[t][1];
        lg[t][2] = __expf(lg[t][2] - mx1); s1 += lg[t][2];
        lg[t][3] = __expf(lg[t][3] - mx1); s1 += lg[t][3];
    }
    s0 += __shfl_xor_sync(0xffffffffu, s0, 1);
    s0 += __shfl_xor_sync(0xffffffffu, s0, 2);
    s1 += __shfl_xor_sync(0xffffffffu, s1, 1);
    s1 += __shfl_xor_sync(0xffffffffu, s1, 2);
    float inv0 = 1.f / s0, inv1 = 1.f / s1;
#pragma unroll
    for (int t = 0; t < 8; t++) {
        int col = t * 8 + 2 * tig;
        MSK[r0 * 65 + col]     = lg[t][0] * inv0;
        MSK[r0 * 65 + col + 1] = lg[t][1] * inv0;
        MSK[r1 * 65 + col]     = lg[t][2] * inv1;
        MSK[r1 * 65 + col + 1] = lg[t][3] * inv1;
    }
    __syncthreads();

    // ---- mask -> global fp16 (packed half2 stores), per-tile partials ----
    size_t mbase = (size_t)b * KCD * HWD + pix0;
    for (int e = tid; e < KCD * MT / 2; e += 256) {
        int k = e >> 6, i2 = e & 63;
        unsigned pv = packh2(MSK[(2 * i2) * 65 + k], MSK[(2 * i2 + 1) * 65 + k]);
        *(unsigned*)(g_maskh + mbase + (size_t)k * HWD + 2 * i2) = pv;
    }
    if (tid < 192) {
        int c = tid >> 6, k = tid & 63;
        float s = 0.f;
        for (int i = 0; i < MT; i++) s += sm[IMG_OFF + c * MT + i] * MSK[i * 65 + k];
        g_wc_part[tile * 192 + tid] = s;
    } else {
        int k = tid - 192;
        float mx = -1e30f, smv = 0.f;
        for (int i = 0; i < MT; i++) {
            float v = MSK[i * 65 + k];
            mx = fmaxf(mx, v); smv += v;
        }
        g_max_part[tile * 64 + k] = mx;
        g_sum_part[tile * 64 + k] = smv;
    }
}

// ---------------------------------------------------------------------------
__global__ __launch_bounds__(256) void k2a_reduce() {
    int job  = blockIdx.x * 8 + (threadIdx.x >> 5);
    int lane = threadIdx.x & 31;
    if (job < 1536) {
        int b = job / 192, r = job % 192;
        const float* p = g_wc_part + (size_t)b * 512 * 192 + r;
        float s = 0.f;
        for (int i = lane; i < 512; i += 32) s += p[(size_t)i * 192];
        for (int o = 16; o; o >>= 1) s += __shfl_xor_sync(0xffffffffu, s, o);
        if (lane == 0) g_wc[job] = s * (1.f / HWD);
    } else if (job < 2048) {
        int j = job - 1536; int b = j >> 6, k = j & 63;
        const float* p = g_max_part + (size_t)b * 512 * 64 + k;
        float m = -1e30f;
        for (int i = lane; i < 512; i += 32) m = fmaxf(m, p[(size_t)i * 64]);
        for (int o = 16; o; o >>= 1) m = fmaxf(m, __shfl_xor_sync(0xffffffffu, m, o));
        if (lane == 0) g_cmax[j] = m;
    } else if (job < 2560) {
        int j = job - 2048; int b = j >> 6, k = j & 63;
        const float* p = g_sum_part + (size_t)b * 512 * 64 + k;
        float s = 0.f;
        for (int i = lane; i < 512; i += 32) s += p[(size_t)i * 64];
        for (int o = 16; o; o >>= 1) s += __shfl_xor_sync(0xffffffffu, s, o);
        if (lane == 0) g_cmean[j] = s * (1.f / HWD);
    }
}

// ---------------------------------------------------------------------------
__global__ __launch_bounds__(512) void k2b_scalars(float* __restrict__ out, int out_size) {
    __shared__ float red[512];
    __shared__ float cmn[512];
    __shared__ float stds[8];
    int t = threadIdx.x;
    red[t] = g_cmax[t];
    cmn[t] = g_cmean[t];
    __syncthreads();
    for (int s = 256; s > 0; s >>= 1) {
        if (t < s) red[t] += red[t + s];
        __syncthreads();
    }
    if (t < 8) {
        float m = 0.f;
        for (int k = 0; k < 64; k++) m += cmn[t * 64 + k];
        m *= (1.f / 64.f);
        float v = 0.f;
        for (int k = 0; k < 64; k++) { float d = cmn[t * 64 + k] - m; v += d * d; }
        stds[t] = sqrtf(v * (1.f / 63.f));
    }
    __syncthreads();
    if (t == 0) {
        float s = 0.f;
        for (int b = 0; b < 8; b++) s += stds[b];
        out[out_size - 2] = red[0] * (1.f / 512.f);
        out[out_size - 1] = s * (1.f / 8.f);
    }
}

// ---------------------------------------------------------------------------
// K3: transformed_img from fp16 mask (half2 loads, 4 px/thread).
// ---------------------------------------------------------------------------
__global__ __launch_bounds__(256) void k3_expand(float* __restrict__ out) {
    int q  = blockIdx.x * 256 + threadIdx.x;   // quad index (4 pixels)
    int b  = q >> 14;
    int pl = (q & 16383) << 2;
    __shared__ float wcs[192];
    if (threadIdx.x < 192) wcs[threadIdx.x] = g_wc[b * 192 + threadIdx.x];
    __syncthreads();
    const __half* mp = g_maskh + (size_t)b * KCD * HWD + pl;
    float4 a0 = {0.f, 0.f, 0.f, 0.f};
    float4 a1 = {0.f, 0.f, 0.f, 0.f};
    float4 a2 = {0.f, 0.f, 0.f, 0.f};
#pragma unroll 8
    for (int k = 0; k < KCD; k++) {
        uint2 mv = *(const uint2*)(mp + (size_t)k * HWD);
        float2 f01 = __half22float2(*(__half2*)&mv.x);
        float2 f23 = __half22float2(*(__half2*)&mv.y);
        float w0 = wcs[k], w1v = wcs[64 + k], w2v = wcs[128 + k];
        a0.x += f01.x * w0;  a0.y += f01.y * w0;  a0.z += f23.x * w0;  a0.w += f23.y * w0;
        a1.x += f01.x * w1v; a1.y += f01.y * w1v; a1.z += f23.x * w1v; a1.w += f23.y * w1v;
        a2.x += f01.x * w2v; a2.y += f01.y * w2v; a2.z += f23.x * w2v; a2.w += f23.y * w2v;
    }
    *(float4*)(out + ((size_t)b * 3 + 0) * HWD + pl) = a0;
    *(float4*)(out + ((size_t)b * 3 + 1) * HWD + pl) = a1;
    *(float4*)(out + ((size_t)b * 3 + 2) * HWD + pl) = a2;
}

// ---------------------------------------------------------------------------
extern "C" void kernel_launch(void* const* d_in, const int* in_sizes, int n_in,
                              void* d_out, int out_size) {
    const float* img  = (const float*)d_in[0];
    const float* feat = (const float*)d_in[1];
    const float* w1 = (const float*)d_in[3];
    const float* b1 = (const float*)d_in[4];
    const float* w2 = (const float*)d_in[5];
    const float* b2 = (const float*)d_in[6];
    float* out = (float*)d_out;

    cudaFuncSetAttribute(k1_mlp, cudaFuncAttributeMaxDynamicSharedMemorySize, SMEM_BYTES);

    k0_prep<<<128, 256>>>(w1, w2);
    k1_mlp<<<NTILES, 256, SMEM_BYTES>>>(feat, img, b1, b2);
    k2a_reduce<<<320, 256>>>();
    k2b_scalars<<<1, 512>>>(out, out_size);
    k3_expand<<<512, 256>>>(out);
}

// round 9
// speedup vs baseline: 1.8458x; 1.0186x over previous
#include <cuda_runtime.h>
#include <cuda_fp16.h>

// ---------------------------------------------------------------------------
// ColorCNN round 9: fp16 mma + 32 rows/warp + uint2 pair-packed weights.
//   Each B-fragment LDS.64 feeds TWO mma (two m-tiles) -> B crossbar bytes
//   per pixel halved, B-LDS instruction count quartered vs round 8.
//   Weights double-buffered (1 CTA/SM, 142KB smem).
// ---------------------------------------------------------------------------

#define HWD   65536
#define NB    8
#define CFD   64
#define HIDD  512
#define KCD   64
#define MT    256
#define NTILES 2048
#define NTHR  256

#define SAO   264   // feat tile stride, words (8 mod 32)
#define S1PW  264   // w1 packed row stride, words (132 uint2)
#define S2PW  136   // w2 packed row stride, words (68 uint2)

// smem word offsets
#define FEAT_OFF 0                     // 64*264 = 16896 (reused as MSK 256*65)
#define W1P0     16896                 // 16*264 = 4224
#define W1P1     21120
#define W2P0     25344                 // 32*136 = 4352
#define W2P1     29696
#define B1_OFF   34048
#define B2_OFF   34560
#define IMG_OFF  34624                 // 768
#define SMEM_FLOATS 35392
#define SMEM_BYTES  (SMEM_FLOATS * 4)  // 141568

#define W1P0U2 (W1P0 / 2)
#define W1P1U2 (W1P1 / 2)
#define W2P0U2 (W2P0 / 2)
#define W2P1U2 (W2P1 / 2)

// global scratch
__device__ __half g_maskh[(size_t)NB * KCD * HWD];
__device__ uint2 g_w1p[16 * HIDD];     // [j*4+tig][n]: (kpair 8j+tig, kpair 8j+tig+4)
__device__ uint2 g_w2p[128 * KCD];     // [ch*32+np*4+tig][n]: (dpair, dpair+4)
__device__ float g_wc_part[NTILES * 192];
__device__ float g_max_part[NTILES * 64];
__device__ float g_sum_part[NTILES * 64];
__device__ float g_wc[NB * 192];
__device__ float g_cmax[NB * KCD];
__device__ float g_cmean[NB * KCD];

__device__ __forceinline__ unsigned packh2(float lo, float hi) {
    unsigned r;
    asm("cvt.rn.f16x2.f32 %0, %1, %2;" : "=r"(r) : "f"(hi), "f"(lo));
    return r;
}

__device__ __forceinline__ void mma16(float c[4], const unsigned a[4],
                                      unsigned b0, unsigned b1) {
    asm volatile(
        "mma.sync.aligned.m16n8k16.row.col.f32.f16.f16.f32 "
        "{%0,%1,%2,%3}, {%4,%5,%6,%7}, {%8,%9}, {%0,%1,%2,%3};"
        : "+f"(c[0]), "+f"(c[1]), "+f"(c[2]), "+f"(c[3])
        : "r"(a[0]), "r"(a[1]), "r"(a[2]), "r"(a[3]),
          "r"(b0), "r"(b1));
}

__device__ __forceinline__ void cpa16(unsigned dst, const void* src) {
    asm volatile("cp.async.cg.shared.global [%0], [%1], 16;" :: "r"(dst), "l"(src));
}
#define CP_COMMIT() asm volatile("cp.async.commit_group;")
#define CP_WAIT0()  asm volatile("cp.async.wait_group 0;")

// ---------------------------------------------------------------------------
// k0_prep: pack weights into paired-uint2 fp16 layout (rn rounding).
// ---------------------------------------------------------------------------
__global__ __launch_bounds__(256) void k0_prep(
    const float* __restrict__ w1, const float* __restrict__ w2)
{
    int i = blockIdx.x * 256 + threadIdx.x;
    if (i < 16 * HIDD) {                      // w1: 16 packed rows x 512
        int row = i >> 9, n = i & 511;
        int j = row >> 2, tg = row & 3;
        int kp = 8 * j + tg;
        uint2 v;
        v.x = packh2(w1[(2 * kp) * HIDD + n],       w1[(2 * kp + 1) * HIDD + n]);
        v.y = packh2(w1[(2 * (kp + 4)) * HIDD + n], w1[(2 * (kp + 4) + 1) * HIDD + n]);
        g_w1p[i] = v;
    } else if (i < 16 * HIDD + 128 * KCD) {   // w2: 128 packed rows x 64
        int idx = i - 16 * HIDD;
        int row = idx >> 6, n = idx & 63;
        int ch = row >> 5, rem = row & 31;
        int np = rem >> 2, tg = rem & 3;
        int dp = ch * 64 + 8 * np + tg;
        uint2 v;
        v.x = packh2(w2[(2 * dp) * KCD + n],       w2[(2 * dp + 1) * KCD + n]);
        v.y = packh2(w2[(2 * (dp + 4)) * KCD + n], w2[(2 * (dp + 4) + 1) * KCD + n]);
        g_w2p[idx] = v;
    }
}

// ---------------------------------------------------------------------------
__global__ __launch_bounds__(NTHR, 1) void k1_mlp(
    const float* __restrict__ feat, const float* __restrict__ img,
    const float* __restrict__ b1, const float* __restrict__ b2)
{
    extern __shared__ float sm[];
    const uint2* usm2 = (const uint2*)sm;
    unsigned smb;
    asm("{ .reg .u64 t; cvta.to.shared.u64 t, %1; cvt.u32.u64 %0, t; }"
        : "=r"(smb) : "l"(sm));

    const int tid  = threadIdx.x;
    const int lane = tid & 31;
    const int wrp  = tid >> 5;
    const int gid  = lane >> 2;
    const int tig  = lane & 3;
    const int tile = blockIdx.x;
    const int b    = tile >> 8;               // 256 tiles per image
    const int pix0 = (tile & 255) * MT;
    const int m0   = wrp * 32;                // 8 warps x 32 rows

    const float* featb = feat + (size_t)b * CFD * HWD + pix0;

    // ---- prologue: feat + w1/w2 chunk 0 via cp.async ----
    for (int it = tid; it < 4096; it += NTHR) {          // feat 64 x 256 f32
        int r = it >> 6, c16 = (it & 63) << 2;
        cpa16(smb + (unsigned)(FEAT_OFF + r * SAO + c16) * 4u,
              featb + (size_t)r * HWD + c16);
    }
    for (int it = tid; it < 1024; it += NTHR) {          // w1 ch0: 16 x 128 u2
        int r = it >> 6, c = it & 63;
        cpa16(smb + (unsigned)(W1P0 + r * S1PW + c * 4) * 4u,
              g_w1p + (size_t)r * HIDD + c * 2);
    }
    for (int it = tid; it < 1024; it += NTHR) {          // w2 ch0: 32 x 64 u2
        int r = it >> 5, c = it & 31;
        cpa16(smb + (unsigned)(W2P0 + r * S2PW + c * 4) * 4u,
              g_w2p + (size_t)r * KCD + c * 2);
    }
    CP_COMMIT();
    if (tid < HIDD) sm[B1_OFF + tid] = b1[tid];          // NTHR=256: two rounds
    if (tid + 256 < HIDD) sm[B1_OFF + tid + 256] = b1[tid + 256];
    if (tid < KCD) sm[B2_OFF + tid] = b2[tid];
    for (int e = tid; e < 3 * MT; e += NTHR)
        sm[IMG_OFF + e] = img[(size_t)b * 3 * HWD + (size_t)(e >> 8) * HWD + pix0 + (e & 255)];
    CP_WAIT0();
    __syncthreads();

    // ---- preload A fragments for both m-tiles ----
    unsigned af[2][4][4];
#pragma unroll
    for (int mt = 0; mt < 2; mt++) {
        int rb = m0 + mt * 16;
#pragma unroll
        for (int kf = 0; kf < 4; kf++) {
            int k0 = 16 * kf + 2 * tig;
            af[mt][kf][0] = packh2(sm[FEAT_OFF + k0 * SAO + rb + gid],
                                   sm[FEAT_OFF + (k0 + 1) * SAO + rb + gid]);
            af[mt][kf][1] = packh2(sm[FEAT_OFF + k0 * SAO + rb + gid + 8],
                                   sm[FEAT_OFF + (k0 + 1) * SAO + rb + gid + 8]);
            af[mt][kf][2] = packh2(sm[FEAT_OFF + (k0 + 8) * SAO + rb + gid],
                                   sm[FEAT_OFF + (k0 + 9) * SAO + rb + gid]);
            af[mt][kf][3] = packh2(sm[FEAT_OFF + (k0 + 8) * SAO + rb + gid + 8],
                                   sm[FEAT_OFF + (k0 + 9) * SAO + rb + gid + 8]);
        }
    }

    float lg[2][8][4];
#pragma unroll
    for (int mt = 0; mt < 2; mt++)
#pragma unroll
        for (int t = 0; t < 8; t++)
            lg[mt][t][0] = lg[mt][t][1] = lg[mt][t][2] = lg[mt][t][3] = 0.f;

    // ---- HID chunk loop, double-buffered weights ----
    for (int ch = 0; ch < 4; ch++) {
        const int cur = ch & 1;
        if (ch < 3) {
            const int nb = (ch + 1) & 1;
            const int d1 = nb ? W1P1 : W1P0;
            const int d2 = nb ? W2P1 : W2P0;
            for (int it = tid; it < 1024; it += NTHR) {
                int r = it >> 6, c = it & 63;
                cpa16(smb + (unsigned)(d1 + r * S1PW + c * 4) * 4u,
                      g_w1p + (size_t)r * HIDD + (ch + 1) * 128 + c * 2);
            }
            for (int it = tid; it < 1024; it += NTHR) {
                int r = it >> 5, c = it & 31;
                cpa16(smb + (unsigned)(d2 + r * S2PW + c * 4) * 4u,
                      g_w2p + (size_t)((ch + 1) * 32 + r) * KCD + c * 2);
            }
            CP_COMMIT();
        }

        const uint2* w1p = usm2 + (cur ? W1P1U2 : W1P0U2);
        const uint2* w2p = usm2 + (cur ? W2P1U2 : W2P0U2);

#pragma unroll 1
        for (int np = 0; np < 8; np++) {
            unsigned a20[4], a21[4];
#pragma unroll
            for (int half = 0; half < 2; half++) {
                const int nt = 2 * np + half;
                const int nc = nt * 8 + gid;
                float c0[4] = {0.f, 0.f, 0.f, 0.f};
                float c1[4] = {0.f, 0.f, 0.f, 0.f};
#pragma unroll
                for (int j = 0; j < 4; j++) {
                    uint2 bb = w1p[(j * 4 + tig) * 132 + nc];
                    mma16(c0, af[0][j], bb.x, bb.y);
                    mma16(c1, af[1][j], bb.x, bb.y);
                }
                int d0 = ch * 128 + nt * 8 + 2 * tig;
                float bb0 = sm[B1_OFF + d0], bb1 = sm[B1_OFF + d0 + 1];
                a20[2 * half]     = packh2(fmaxf(c0[0] + bb0, 0.f), fmaxf(c0[1] + bb1, 0.f));
                a20[2 * half + 1] = packh2(fmaxf(c0[2] + bb0, 0.f), fmaxf(c0[3] + bb1, 0.f));
                a21[2 * half]     = packh2(fmaxf(c1[0] + bb0, 0.f), fmaxf(c1[1] + bb1, 0.f));
                a21[2 * half + 1] = packh2(fmaxf(c1[2] + bb0, 0.f), fmaxf(c1[3] + bb1, 0.f));
            }
#pragma unroll
            for (int t = 0; t < 8; t++) {
                uint2 bb = w2p[(np * 4 + tig) * 68 + t * 8 + gid];
                mma16(lg[0][t], a20, bb.x, bb.y);
                mma16(lg[1][t], a21, bb.x, bb.y);
            }
        }

        if (ch < 3) {
            CP_WAIT0();
            __syncthreads();
        }
    }
    __syncthreads();   // weight reads done; FEAT region -> MSK

    // ---- softmax per m-tile (quad reductions, fp32) ----
    float* MSK = sm + FEAT_OFF;   // stride 65, 256 rows
#pragma unroll
    for (int mt = 0; mt < 2; mt++) {
        const int r0 = m0 + mt * 16 + gid, r1 = r0 + 8;
        float mx0 = -1e30f, mx1 = -1e30f;
#pragma unroll
        for (int t = 0; t < 8; t++) {
            int col = t * 8 + 2 * tig;
            float bb0 = sm[B2_OFF + col], bb1 = sm[B2_OFF + col + 1];
            lg[mt][t][0] += bb0; lg[mt][t][1] += bb1;
            lg[mt][t][2] += bb0; lg[mt][t][3] += bb1;
            mx0 = fmaxf(mx0, fmaxf(lg[mt][t][0], lg[mt][t][1]));
            mx1 = fmaxf(mx1, fmaxf(lg[mt][t][2], lg[mt][t][3]));
        }
        mx0 = fmaxf(mx0, __shfl_xor_sync(0xffffffffu, mx0, 1));
        mx0 = fmaxf(mx0, __shfl_xor_sync(0xffffffffu, mx0, 2));
        mx1 = fmaxf(mx1, __shfl_xor_sync(0xffffffffu, mx1, 1));
        mx1 = fmaxf(mx1, __shfl_xor_sync(0xffffffffu, mx1, 2));
        float s0 = 0.f, s1 = 0.f;
#pragma unroll
        for (int t = 0; t < 8; t++) {
            lg[mt][t][0] = __expf(lg[mt][t][0] - mx0); s0 += lg[mt][t][0];
            lg[mt][t][1] = __expf(lg[mt][t][1] - mx0); s0 += lg[mt][t][1];
            lg[mt][t][2] = __expf(lg[mt][t][2] - mx1); s1 += lg[mt][t][2];
            lg[mt][t][3] = __expf(lg[mt][t][3] - mx1); s1 += lg[mt][t][3];
        }
        s0 += __shfl_xor_sync(0xffffffffu, s0, 1);
        s0 += __shfl_xor_sync(0xffffffffu, s0, 2);
        s1 += __shfl_xor_sync(0xffffffffu, s1, 1);
        s1 += __shfl_xor_sync(0xffffffffu, s1, 2);
        float inv0 = 1.f / s0, inv1 = 1.f / s1;
#pragma unroll
        for (int t = 0; t < 8; t++) {
            int col = t * 8 + 2 * tig;
            MSK[r0 * 65 + col]     = lg[mt][t][0] * inv0;
            MSK[r0 * 65 + col + 1] = lg[mt][t][1] * inv0;
            MSK[r1 * 65 + col]     = lg[mt][t][2] * inv1;
            MSK[r1 * 65 + col + 1] = lg[mt][t][3] * inv1;
        }
    }
    __syncthreads();

    // ---- mask -> global fp16 (uint2 = 4 px), per-tile partials ----
    size_t mbase = (size_t)b * KCD * HWD + pix0;
    for (int e = tid; e < KCD * MT / 4; e += NTHR) {
        int k = e >> 6, i4 = (e & 63) << 2;
        uint2 pv;
        pv.x = packh2(MSK[i4 * 65 + k],       MSK[(i4 + 1) * 65 + k]);
        pv.y = packh2(MSK[(i4 + 2) * 65 + k], MSK[(i4 + 3) * 65 + k]);
        *(uint2*)(g_maskh + mbase + (size_t)k * HWD + i4) = pv;
    }
    if (tid < 192) {
        int c = tid >> 6, k = tid & 63;
        float s = 0.f;
        for (int i = 0; i < MT; i++) s += sm[IMG_OFF + c * MT + i] * MSK[i * 65 + k];
        g_wc_part[tile * 192 + tid] = s;
    } else {
        int k = tid - 192;
        float mx = -1e30f, smv = 0.f;
        for (int i = 0; i < MT; i++) {
            float v = MSK[i * 65 + k];
            mx = fmaxf(mx, v); smv += v;
        }
        g_max_part[tile * 64 + k] = mx;
        g_sum_part[tile * 64 + k] = smv;
    }
}

// ---------------------------------------------------------------------------
__global__ __launch_bounds__(256) void k2a_reduce() {
    int job  = blockIdx.x * 8 + (threadIdx.x >> 5);
    int lane = threadIdx.x & 31;
    if (job < 1536) {
        int b = job / 192, r = job % 192;
        const float* p = g_wc_part + (size_t)b * 256 * 192 + r;
        float s = 0.f;
        for (int i = lane; i < 256; i += 32) s += p[(size_t)i * 192];
        for (int o = 16; o; o >>= 1) s += __shfl_xor_sync(0xffffffffu, s, o);
        if (lane == 0) g_wc[job] = s * (1.f / HWD);
    } else if (job < 2048) {
        int j = job - 1536; int b = j >> 6, k = j & 63;
        const float* p = g_max_part + (size_t)b * 256 * 64 + k;
        float m = -1e30f;
        for (int i = lane; i < 256; i += 32) m = fmaxf(m, p[(size_t)i * 64]);
        for (int o = 16; o; o >>= 1) m = fmaxf(m, __shfl_xor_sync(0xffffffffu, m, o));
        if (lane == 0) g_cmax[j] = m;
    } else if (job < 2560) {
        int j = job - 2048; int b = j >> 6, k = j & 63;
        const float* p = g_sum_part + (size_t)b * 256 * 64 + k;
        float s = 0.f;
        for (int i = lane; i < 256; i += 32) s += p[(size_t)i * 64];
        for (int o = 16; o; o >>= 1) s += __shfl_xor_sync(0xffffffffu, s, o);
        if (lane == 0) g_cmean[j] = s * (1.f / HWD);
    }
}

// ---------------------------------------------------------------------------
__global__ __launch_bounds__(512) void k2b_scalars(float* __restrict__ out, int out_size) {
    __shared__ float red[512];
    __shared__ float cmn[512];
    __shared__ float stds[8];
    int t = threadIdx.x;
    red[t] = g_cmax[t];
    cmn[t] = g_cmean[t];
    __syncthreads();
    for (int s = 256; s > 0; s >>= 1) {
        if (t < s) red[t] += red[t + s];
        __syncthreads();
    }
    if (t < 8) {
        float m = 0.f;
        for (int k = 0; k < 64; k++) m += cmn[t * 64 + k];
        m *= (1.f / 64.f);
        float v = 0.f;
        for (int k = 0; k < 64; k++) { float d = cmn[t * 64 + k] - m; v += d * d; }
        stds[t] = sqrtf(v * (1.f / 63.f));
    }
    __syncthreads();
    if (t == 0) {
        float s = 0.f;
        for (int b = 0; b < 8; b++) s += stds[b];
        out[out_size - 2] = red[0] * (1.f / 512.f);
        out[out_size - 1] = s * (1.f / 8.f);
    }
}

// ---------------------------------------------------------------------------
__global__ __launch_bounds__(256) void k3_expand(float* __restrict__ out) {
    int q  = blockIdx.x * 256 + threadIdx.x;
    int b  = q >> 14;
    int pl = (q & 16383) << 2;
    __shared__ float wcs[192];
    if (threadIdx.x < 192) wcs[threadIdx.x] = g_wc[b * 192 + threadIdx.x];
    __syncthreads();
    const __half* mp = g_maskh + (size_t)b * KCD * HWD + pl;
    float4 a0 = {0.f, 0.f, 0.f, 0.f};
    float4 a1 = {0.f, 0.f, 0.f, 0.f};
    float4 a2 = {0.f, 0.f, 0.f, 0.f};
#pragma unroll 8
    for (int k = 0; k < KCD; k++) {
        uint2 mv = *(const uint2*)(mp + (size_t)k * HWD);
        float2 f01 = __half22float2(*(__half2*)&mv.x);
        float2 f23 = __half22float2(*(__half2*)&mv.y);
        float w0 = wcs[k], w1v = wcs[64 + k], w2v = wcs[128 + k];
        a0.x += f01.x * w0;  a0.y += f01.y * w0;  a0.z += f23.x * w0;  a0.w += f23.y * w0;
        a1.x += f01.x * w1v; a1.y += f01.y * w1v; a1.z += f23.x * w1v; a1.w += f23.y * w1v;
        a2.x += f01.x * w2v; a2.y += f01.y * w2v; a2.z += f23.x * w2v; a2.w += f23.y * w2v;
    }
    *(float4*)(out + ((size_t)b * 3 + 0) * HWD + pl) = a0;
    *(float4*)(out + ((size_t)b * 3 + 1) * HWD + pl) = a1;
    *(float4*)(out + ((size_t)b * 3 + 2) * HWD + pl) = a2;
}

// ---------------------------------------------------------------------------
extern "C" void kernel_launch(void* const* d_in, const int* in_sizes, int n_in,
                              void* d_out, int out_size) {
    const float* img  = (const float*)d_in[0];
    const float* feat = (const float*)d_in[1];
    const float* w1 = (const float*)d_in[3];
    const float* b1 = (const float*)d_in[4];
    const float* w2 = (const float*)d_in[5];
    const float* b2 = (const float*)d_in[6];
    float* out = (float*)d_out;

    cudaFuncSetAttribute(k1_mlp, cudaFuncAttributeMaxDynamicSharedMemorySize, SMEM_BYTES);

    k0_prep<<<64, 256>>>(w1, w2);
    k1_mlp<<<NTILES, NTHR, SMEM_BYTES>>>(feat, img, b1, b2);
    k2a_reduce<<<320, 256>>>();
    k2b_scalars<<<1, 512>>>(out, out_size);
    k3_expand<<<512, 256>>>(out);
}